// round 2
// baseline (speedup 1.0000x reference)
#include <cuda_runtime.h>

#define NB 2048
#define NT 100
#define ND 128
#define NH 256
#define NW 256
#define K4 1024            // 4*NH
#define KIN 384            // ND + NH
#define NEG_FILLF (-1.0e9f)
#define PROB_MINF (1e-9f)

// ---------------- scratch (static device globals; no allocations) ----------------
__device__ float g_Wenc[KIN * K4];     // reordered enc weights [k][j*4+g]
__device__ float g_Wdec[KIN * K4];     // reordered dec weights
__device__ float g_benc[K4];
__device__ float g_bdec[K4];
__device__ float g_W1t[NH * NW];       // W1^T : [k][w]
__device__ float g_W2t[NH * NW];       // W2^T : [k][w]
__device__ float g_hA[NB * NH];
__device__ float g_hB[NB * NH];
__device__ float g_c[NB * NH];
__device__ float g_hdA[NB * NH];
__device__ float g_hdB[NB * NH];
__device__ float g_cd[NB * NH];
__device__ float g_enc[(size_t)NB * NT * NH];     // encoder states [b][t][h]
__device__ float g_blend1[(size_t)NB * NT * NW];  // [b][t][w]
__device__ float g_decin[NB * ND];
__device__ int   g_mask[NB * NT];

// ---------------- fast activations (MUFU-based, ~1e-7 rel err) ----------------
__device__ __forceinline__ float fast_sigmoid(float x) {
    return __fdividef(1.f, 1.f + __expf(-x));
}
__device__ __forceinline__ float fast_tanh(float x) {
    // 2*sigmoid(2x)-1 ; saturates correctly at +/-1 for large |x|
    return 2.f * __fdividef(1.f, 1.f + __expf(-2.f * x)) - 1.f;
}

// ---------------- init: reset all recurrent state every call ----------------
__global__ void init_kernel(const float* __restrict__ h0, const float* __restrict__ c0) {
    int idx = blockIdx.x * blockDim.x + threadIdx.x;   // 524288 total (NB*NH)
    g_hA[idx]  = 0.f;
    g_c[idx]   = 0.f;
    g_hdA[idx] = h0[idx];
    g_cd[idx]  = c0[idx];
    if (idx < NB * ND) g_decin[idx] = 0.f;
    if (idx < NB * NT) g_mask[idx]  = 0;
}

// ---------------- prep: weight reorder + transposes + bias fold ----------------
__global__ void prep_kernel(const float* __restrict__ ewih, const float* __restrict__ ewhh,
                            const float* __restrict__ ebih, const float* __restrict__ ebhh,
                            const float* __restrict__ dwih, const float* __restrict__ dwhh,
                            const float* __restrict__ dbih, const float* __restrict__ dbhh,
                            const float* __restrict__ W1,   const float* __restrict__ W2) {
    int idx = blockIdx.x * blockDim.x + threadIdx.x;   // 393216 total
    if (idx < KIN * K4) {
        int k = idx >> 10, col = idx & 1023;
        int j = col >> 2, g = col & 3;
        int sr = g * NH + j;               // PyTorch gate-major row (i,f,g,o)
        g_Wenc[idx] = (k < ND) ? ewih[sr * ND + k] : ewhh[sr * NH + (k - ND)];
        g_Wdec[idx] = (k < ND) ? dwih[sr * ND + k] : dwhh[sr * NH + (k - ND)];
    }
    if (idx < NH * NW) {
        int k = idx >> 8, w = idx & 255;
        g_W1t[idx] = W1[w * NH + k];
        g_W2t[idx] = W2[w * NH + k];
    }
    if (idx < K4) {
        int j = idx >> 2, g = idx & 3;
        int sr = g * NH + j;
        g_benc[idx] = ebih[sr] + ebhh[sr];
        g_bdec[idx] = dbih[sr] + dbhh[sr];
    }
}

// ---------------- fused LSTM step: tiled GEMM (K=384) + cell update epilogue ----------------
// C[b, j*4+g] = concat(x[b], h[b]) @ Wr ; epilogue applies the LSTM cell.
// Tiles: BM=64 rows, BN=128 cols (=32 j's), BK=16. 256 threads, 8x4 micro-tile.
__global__ __launch_bounds__(256) void lstm_step_kernel(const float* __restrict__ targets,
                                                        int t, int is_dec) {
    __shared__ float As[16][68];   // padded (2-way STS conflict max)
    __shared__ float Bs[16][128];

    const float* X; long xrs;
    const float* Wr; const float* bias; const float* hin;
    float* hout; float* cst; float* eo;
    if (is_dec) {
        X = g_decin; xrs = ND; Wr = g_Wdec; bias = g_bdec;
        hin  = (t & 1) ? g_hdB : g_hdA;
        hout = (t & 1) ? g_hdA : g_hdB;
        cst = g_cd; eo = nullptr;
    } else {
        X = targets + (long)t * ND; xrs = (long)NT * ND; Wr = g_Wenc; bias = g_benc;
        hin  = (t & 1) ? g_hB : g_hA;
        hout = (t & 1) ? g_hA : g_hB;
        cst = g_c; eo = g_enc + (long)t * NH;
    }

    int tid = threadIdx.x;
    int tc = tid & 31, tr = tid >> 5;
    int rb0 = blockIdx.y * 64, nb0 = blockIdx.x * 128;

    float acc[8][4];
#pragma unroll
    for (int i = 0; i < 8; i++)
#pragma unroll
        for (int j2 = 0; j2 < 4; j2++) acc[i][j2] = 0.f;

    int am = tid >> 2;          // 0..63 : A row within tile
    int ak = (tid & 3) * 4;     // 0,4,8,12 : A k-quad

    for (int k0 = 0; k0 < KIN; k0 += 16) {
        int kk = k0 + ak;
        int row = rb0 + am;
        float4 av;
        if (kk < ND) av = *(const float4*)&X[(long)row * xrs + kk];
        else         av = *(const float4*)&hin[(long)row * NH + (kk - ND)];
        As[ak + 0][am] = av.x; As[ak + 1][am] = av.y;
        As[ak + 2][am] = av.z; As[ak + 3][am] = av.w;
#pragma unroll
        for (int p = 0; p < 2; p++) {
            int idx = tid + p * 256;
            int n = (idx & 31) * 4, k = idx >> 5;
            *(float4*)&Bs[k][n] = *(const float4*)&Wr[(long)(k0 + k) * K4 + nb0 + n];
        }
        __syncthreads();
#pragma unroll
        for (int k = 0; k < 16; k++) {
            float4 a0 = *(const float4*)&As[k][tr * 8];
            float4 a1 = *(const float4*)&As[k][tr * 8 + 4];
            float4 bv = *(const float4*)&Bs[k][tc * 4];
            float a[8] = {a0.x, a0.y, a0.z, a0.w, a1.x, a1.y, a1.z, a1.w};
            float b[4] = {bv.x, bv.y, bv.z, bv.w};
#pragma unroll
            for (int i = 0; i < 8; i++)
#pragma unroll
                for (int j2 = 0; j2 < 4; j2++) acc[i][j2] += a[i] * b[j2];
        }
        __syncthreads();
    }

    int j = (nb0 >> 2) + tc;   // global hidden index 0..255
    float b0 = bias[nb0 + tc * 4 + 0];
    float b1 = bias[nb0 + tc * 4 + 1];
    float b2 = bias[nb0 + tc * 4 + 2];
    float b3 = bias[nb0 + tc * 4 + 3];
#pragma unroll
    for (int i = 0; i < 8; i++) {
        int row = rb0 + tr * 8 + i;
        float gi = acc[i][0] + b0;
        float gf = acc[i][1] + b1;
        float gg = acc[i][2] + b2;
        float go = acc[i][3] + b3;
        float si = fast_sigmoid(gi);
        float sf = fast_sigmoid(gf);
        float so = fast_sigmoid(go);
        float tg = fast_tanh(gg);
        long cix = (long)row * NH + j;
        float cn = sf * cst[cix] + si * tg;
        float hn = so * fast_tanh(cn);
        cst[cix] = cn;
        hout[(long)row * NH + j] = hn;
        if (eo) eo[(long)row * ((long)NT * NH) + j] = hn;
    }
}

// ---------------- blend1 = enc_states @ W1^T  (M=204800, N=256, K=256) ----------------
__global__ __launch_bounds__(256) void blend1_kernel() {
    __shared__ float As[16][68];
    __shared__ float Bs[16][128];
    int tid = threadIdx.x;
    int tc = tid & 31, tr = tid >> 5;
    long rb0 = (long)blockIdx.y * 64;
    int nb0 = blockIdx.x * 128;

    float acc[8][4];
#pragma unroll
    for (int i = 0; i < 8; i++)
#pragma unroll
        for (int j2 = 0; j2 < 4; j2++) acc[i][j2] = 0.f;

    int am = tid >> 2;
    int ak = (tid & 3) * 4;

    for (int k0 = 0; k0 < NH; k0 += 16) {
        long row = rb0 + am;
        float4 av = *(const float4*)&g_enc[row * NH + k0 + ak];
        As[ak + 0][am] = av.x; As[ak + 1][am] = av.y;
        As[ak + 2][am] = av.z; As[ak + 3][am] = av.w;
#pragma unroll
        for (int p = 0; p < 2; p++) {
            int idx = tid + p * 256;
            int n = (idx & 31) * 4, k = idx >> 5;
            *(float4*)&Bs[k][n] = *(const float4*)&g_W1t[(k0 + k) * NW + nb0 + n];
        }
        __syncthreads();
#pragma unroll
        for (int k = 0; k < 16; k++) {
            float4 a0 = *(const float4*)&As[k][tr * 8];
            float4 a1 = *(const float4*)&As[k][tr * 8 + 4];
            float4 bv = *(const float4*)&Bs[k][tc * 4];
            float a[8] = {a0.x, a0.y, a0.z, a0.w, a1.x, a1.y, a1.z, a1.w};
            float b[4] = {bv.x, bv.y, bv.z, bv.w};
#pragma unroll
            for (int i = 0; i < 8; i++)
#pragma unroll
                for (int j2 = 0; j2 < 4; j2++) acc[i][j2] += a[i] * b[j2];
        }
        __syncthreads();
    }
#pragma unroll
    for (int i = 0; i < 8; i++) {
        long row = rb0 + tr * 8 + i;
        float4 cv = make_float4(acc[i][0], acc[i][1], acc[i][2], acc[i][3]);
        *(float4*)&g_blend1[row * NW + nb0 + tc * 4] = cv;
    }
}

// ---------------- pointer attention step: blend2 + scores + argmax + softmax + gather ----------------
__global__ __launch_bounds__(256) void attn_kernel(const float* __restrict__ targets,
                                                   const float* __restrict__ vt,
                                                   float* __restrict__ out, int step) {
    int b = blockIdx.x, tid = threadIdx.x;
    int lane = tid & 31, warp = tid >> 5;
    __shared__ float hs[NH], b2s[NW], vts[NW], sc[NT];
    __shared__ float red[8];
    __shared__ float mx_s, tot_s;
    __shared__ int sel_s;

    const float* hd = (step & 1) ? g_hdA : g_hdB;   // h written by this step's LSTM
    hs[tid]  = hd[(long)b * NH + tid];
    vts[tid] = vt[tid];
    __syncthreads();

    // blend2[w] = h . W2[w,:]  via transposed weights (coalesced)
    float acc = 0.f;
#pragma unroll 8
    for (int k = 0; k < NH; k++) acc += hs[k] * g_W2t[k * NW + tid];
    b2s[tid] = acc;
    __syncthreads();

    // scores over T, one warp per t (strided)
    for (int tt = warp; tt < NT; tt += 8) {
        const float* bl = &g_blend1[((long)b * NT + tt) * NW];
        float s = 0.f;
#pragma unroll
        for (int q = 0; q < NW / 32; q++) {
            int w = lane + q * 32;
            s += fast_tanh(bl[w] + b2s[w]) * vts[w];
        }
#pragma unroll
        for (int o = 16; o; o >>= 1) s += __shfl_down_sync(0xffffffffu, s, o);
        if (lane == 0) sc[tt] = g_mask[b * NT + tt] ? NEG_FILLF : s;
    }
    __syncthreads();

    // argmax (first occurrence of max, matching jnp.argmax)
    if (tid == 0) {
        float mx = sc[0]; int mi = 0;
        for (int tt = 1; tt < NT; tt++)
            if (sc[tt] > mx) { mx = sc[tt]; mi = tt; }
        sel_s = mi; mx_s = mx;
    }
    __syncthreads();

    // softmax with clamp
    float e = (tid < NT) ? __expf(sc[tid] - mx_s) : 0.f;
    float s2 = e;
#pragma unroll
    for (int o = 16; o; o >>= 1) s2 += __shfl_down_sync(0xffffffffu, s2, o);
    if (lane == 0) red[warp] = s2;
    __syncthreads();
    if (tid == 0) {
        float tot = 0.f;
        for (int w = 0; w < 8; w++) tot += red[w];
        tot_s = tot;
    }
    __syncthreads();
    if (tid < NT) {
        float p = e / tot_s;
        if (p < PROB_MINF) p = PROB_MINF;
        out[((long)b * NT + step) * NT + tid] = p;
    }

    // mask update AFTER probs (matches reference ordering) + gather next input
    int sel = sel_s;
    if (tid == 0) g_mask[b * NT + sel] = 1;
    if (tid < ND) g_decin[(long)b * ND + tid] = targets[((long)b * NT + sel) * ND + tid];
}

// ---------------- launch ----------------
extern "C" void kernel_launch(void* const* d_in, const int* in_sizes, int n_in,
                              void* d_out, int out_size) {
    const float* targets = (const float*)d_in[0];
    const float* h0      = (const float*)d_in[1];
    const float* c0      = (const float*)d_in[2];
    const float* ewih    = (const float*)d_in[3];
    const float* ewhh    = (const float*)d_in[4];
    const float* ebih    = (const float*)d_in[5];
    const float* ebhh    = (const float*)d_in[6];
    const float* dwih    = (const float*)d_in[7];
    const float* dwhh    = (const float*)d_in[8];
    const float* dbih    = (const float*)d_in[9];
    const float* dbhh    = (const float*)d_in[10];
    const float* W1      = (const float*)d_in[11];
    const float* W2      = (const float*)d_in[12];
    const float* vt      = (const float*)d_in[13];
    float* out = (float*)d_out;

    init_kernel<<<(NB * NH) / 256, 256>>>(h0, c0);
    prep_kernel<<<(KIN * K4) / 256, 256>>>(ewih, ewhh, ebih, ebhh,
                                           dwih, dwhh, dbih, dbhh, W1, W2);

    dim3 lgrid(K4 / 128, NB / 64);   // (8, 32)
    for (int t = 0; t < NT; t++)
        lstm_step_kernel<<<lgrid, 256>>>(targets, t, 0);

    blend1_kernel<<<dim3(NW / 128, (NB * NT) / 64), 256>>>();   // (2, 3200)

    for (int s = 0; s < NT; s++) {
        lstm_step_kernel<<<lgrid, 256>>>(targets, s, 1);
        attn_kernel<<<NB, 256>>>(targets, vt, out, s);
    }
}

// round 4
// speedup vs baseline: 1.0036x; 1.0036x over previous
#include <cuda_runtime.h>

#define NB 2048
#define NT 100
#define ND 128
#define NH 256
#define NW 256
#define K4 1024            // 4*NH
#define KIN 384            // ND + NH
#define NEG_FILLF (-1.0e9f)
#define PROB_MINF (1e-9f)

// ---------------- scratch (static device globals; no allocations) ----------------
__device__ float g_Wenc[KIN * K4];     // reordered enc weights [k][j*4+g]
__device__ float g_Wdec[KIN * K4];     // reordered dec weights
__device__ float g_benc[K4];
__device__ float g_bdec[K4];
__device__ float g_W1t[NH * NW];       // W1^T : [k][w]
__device__ float g_W2t[NH * NW];       // W2^T : [k][w]
__device__ float g_hA[NB * NH];
__device__ float g_hB[NB * NH];
__device__ float g_c[NB * NH];
__device__ float g_hdA[NB * NH];
__device__ float g_hdB[NB * NH];
__device__ float g_cd[NB * NH];
__device__ float g_enc[(size_t)NB * NT * NH];     // encoder states [b][t][h]
__device__ float g_blend1[(size_t)NB * NT * NW];  // [b][t][w]
__device__ float g_decin[NB * ND];
__device__ int   g_mask[NB * NT];

// ---------------- fast activations (MUFU-based, ~1e-7 rel err) ----------------
__device__ __forceinline__ float fast_sigmoid(float x) {
    return __fdividef(1.f, 1.f + __expf(-x));
}
__device__ __forceinline__ float fast_tanh(float x) {
    // 2*sigmoid(2x)-1 ; saturates correctly at +/-1 for large |x|
    return 2.f * __fdividef(1.f, 1.f + __expf(-2.f * x)) - 1.f;
}

// ---------------- init: reset all recurrent state every call ----------------
__global__ void init_kernel(const float* __restrict__ h0, const float* __restrict__ c0) {
    int idx = blockIdx.x * blockDim.x + threadIdx.x;   // 524288 total (NB*NH)
    g_hA[idx]  = 0.f;
    g_c[idx]   = 0.f;
    g_hdA[idx] = h0[idx];
    g_cd[idx]  = c0[idx];
    if (idx < NB * ND) g_decin[idx] = 0.f;
    if (idx < NB * NT) g_mask[idx]  = 0;
}

// ---------------- prep: weight reorder + transposes + bias fold ----------------
__global__ void prep_kernel(const float* __restrict__ ewih, const float* __restrict__ ewhh,
                            const float* __restrict__ ebih, const float* __restrict__ ebhh,
                            const float* __restrict__ dwih, const float* __restrict__ dwhh,
                            const float* __restrict__ dbih, const float* __restrict__ dbhh,
                            const float* __restrict__ W1,   const float* __restrict__ W2) {
    int idx = blockIdx.x * blockDim.x + threadIdx.x;   // 393216 total
    if (idx < KIN * K4) {
        int k = idx >> 10, col = idx & 1023;
        int j = col >> 2, g = col & 3;
        int sr = g * NH + j;               // PyTorch gate-major row (i,f,g,o)
        g_Wenc[idx] = (k < ND) ? ewih[sr * ND + k] : ewhh[sr * NH + (k - ND)];
        g_Wdec[idx] = (k < ND) ? dwih[sr * ND + k] : dwhh[sr * NH + (k - ND)];
    }
    if (idx < NH * NW) {
        int k = idx >> 8, w = idx & 255;
        g_W1t[idx] = W1[w * NH + k];
        g_W2t[idx] = W2[w * NH + k];
    }
    if (idx < K4) {
        int j = idx >> 2, g = idx & 3;
        int sr = g * NH + j;
        g_benc[idx] = ebih[sr] + ebhh[sr];
        g_bdec[idx] = dbih[sr] + dbhh[sr];
    }
}

// ---------------- fused LSTM step: tiled GEMM (K=384) + cell update epilogue ----------------
// C[b, j*4+g] = concat(x[b], h[b]) @ Wr ; epilogue applies the LSTM cell.
// Tiles: BM=64 rows, BN=128 cols (=32 j's), BK=16. 256 threads, 8x4 micro-tile.
__global__ __launch_bounds__(256) void lstm_step_kernel(const float* __restrict__ targets,
                                                        int t, int is_dec) {
    __shared__ float As[16][68];   // padded (2-way STS conflict max)
    __shared__ float Bs[16][128];

    const float* X; long xrs;
    const float* Wr; const float* bias; const float* hin;
    float* hout; float* cst; float* eo;
    if (is_dec) {
        X = g_decin; xrs = ND; Wr = g_Wdec; bias = g_bdec;
        hin  = (t & 1) ? g_hdB : g_hdA;
        hout = (t & 1) ? g_hdA : g_hdB;
        cst = g_cd; eo = nullptr;
    } else {
        X = targets + (long)t * ND; xrs = (long)NT * ND; Wr = g_Wenc; bias = g_benc;
        hin  = (t & 1) ? g_hB : g_hA;
        hout = (t & 1) ? g_hA : g_hB;
        cst = g_c; eo = g_enc + (long)t * NH;
    }

    int tid = threadIdx.x;
    int tc = tid & 31, tr = tid >> 5;
    int rb0 = blockIdx.y * 64, nb0 = blockIdx.x * 128;

    float acc[8][4];
#pragma unroll
    for (int i = 0; i < 8; i++)
#pragma unroll
        for (int j2 = 0; j2 < 4; j2++) acc[i][j2] = 0.f;

    int am = tid >> 2;          // 0..63 : A row within tile
    int ak = (tid & 3) * 4;     // 0,4,8,12 : A k-quad

    for (int k0 = 0; k0 < KIN; k0 += 16) {
        int kk = k0 + ak;
        int row = rb0 + am;
        float4 av;
        if (kk < ND) av = *(const float4*)&X[(long)row * xrs + kk];
        else         av = *(const float4*)&hin[(long)row * NH + (kk - ND)];
        As[ak + 0][am] = av.x; As[ak + 1][am] = av.y;
        As[ak + 2][am] = av.z; As[ak + 3][am] = av.w;
#pragma unroll
        for (int p = 0; p < 2; p++) {
            int idx = tid + p * 256;
            int n = (idx & 31) * 4, k = idx >> 5;
            *(float4*)&Bs[k][n] = *(const float4*)&Wr[(long)(k0 + k) * K4 + nb0 + n];
        }
        __syncthreads();
#pragma unroll
        for (int k = 0; k < 16; k++) {
            float4 a0 = *(const float4*)&As[k][tr * 8];
            float4 a1 = *(const float4*)&As[k][tr * 8 + 4];
            float4 bv = *(const float4*)&Bs[k][tc * 4];
            float a[8] = {a0.x, a0.y, a0.z, a0.w, a1.x, a1.y, a1.z, a1.w};
            float b[4] = {bv.x, bv.y, bv.z, bv.w};
#pragma unroll
            for (int i = 0; i < 8; i++)
#pragma unroll
                for (int j2 = 0; j2 < 4; j2++) acc[i][j2] += a[i] * b[j2];
        }
        __syncthreads();
    }

    int j = (nb0 >> 2) + tc;   // global hidden index 0..255
    float b0 = bias[nb0 + tc * 4 + 0];
    float b1 = bias[nb0 + tc * 4 + 1];
    float b2 = bias[nb0 + tc * 4 + 2];
    float b3 = bias[nb0 + tc * 4 + 3];
#pragma unroll
    for (int i = 0; i < 8; i++) {
        int row = rb0 + tr * 8 + i;
        float gi = acc[i][0] + b0;
        float gf = acc[i][1] + b1;
        float gg = acc[i][2] + b2;
        float go = acc[i][3] + b3;
        float si = fast_sigmoid(gi);
        float sf = fast_sigmoid(gf);
        float so = fast_sigmoid(go);
        float tg = fast_tanh(gg);
        long cix = (long)row * NH + j;
        float cn = sf * cst[cix] + si * tg;
        float hn = so * fast_tanh(cn);
        cst[cix] = cn;
        hout[(long)row * NH + j] = hn;
        if (eo) eo[(long)row * ((long)NT * NH) + j] = hn;
    }
}

// ---------------- blend1 = enc_states @ W1^T  (M=204800, N=256, K=256) ----------------
__global__ __launch_bounds__(256) void blend1_kernel() {
    __shared__ float As[16][68];
    __shared__ float Bs[16][128];
    int tid = threadIdx.x;
    int tc = tid & 31, tr = tid >> 5;
    long rb0 = (long)blockIdx.y * 64;
    int nb0 = blockIdx.x * 128;

    float acc[8][4];
#pragma unroll
    for (int i = 0; i < 8; i++)
#pragma unroll
        for (int j2 = 0; j2 < 4; j2++) acc[i][j2] = 0.f;

    int am = tid >> 2;
    int ak = (tid & 3) * 4;

    for (int k0 = 0; k0 < NH; k0 += 16) {
        long row = rb0 + am;
        float4 av = *(const float4*)&g_enc[row * NH + k0 + ak];
        As[ak + 0][am] = av.x; As[ak + 1][am] = av.y;
        As[ak + 2][am] = av.z; As[ak + 3][am] = av.w;
#pragma unroll
        for (int p = 0; p < 2; p++) {
            int idx = tid + p * 256;
            int n = (idx & 31) * 4, k = idx >> 5;
            *(float4*)&Bs[k][n] = *(const float4*)&g_W1t[(k0 + k) * NW + nb0 + n];
        }
        __syncthreads();
#pragma unroll
        for (int k = 0; k < 16; k++) {
            float4 a0 = *(const float4*)&As[k][tr * 8];
            float4 a1 = *(const float4*)&As[k][tr * 8 + 4];
            float4 bv = *(const float4*)&Bs[k][tc * 4];
            float a[8] = {a0.x, a0.y, a0.z, a0.w, a1.x, a1.y, a1.z, a1.w};
            float b[4] = {bv.x, bv.y, bv.z, bv.w};
#pragma unroll
            for (int i = 0; i < 8; i++)
#pragma unroll
                for (int j2 = 0; j2 < 4; j2++) acc[i][j2] += a[i] * b[j2];
        }
        __syncthreads();
    }
#pragma unroll
    for (int i = 0; i < 8; i++) {
        long row = rb0 + tr * 8 + i;
        float4 cv = make_float4(acc[i][0], acc[i][1], acc[i][2], acc[i][3]);
        *(float4*)&g_blend1[row * NW + nb0 + tc * 4] = cv;
    }
}

// ---------------- pointer attention step: blend2 + scores + argmax + softmax + gather ----------------
__global__ __launch_bounds__(256) void attn_kernel(const float* __restrict__ targets,
                                                   const float* __restrict__ vt,
                                                   float* __restrict__ out, int step) {
    int b = blockIdx.x, tid = threadIdx.x;
    int lane = tid & 31, warp = tid >> 5;
    __shared__ float hs[NH], b2s[NW], vts[NW], sc[NT];
    __shared__ float red[8];
    __shared__ float mx_s, tot_s;
    __shared__ int sel_s;

    const float* hd = (step & 1) ? g_hdA : g_hdB;   // h written by this step's LSTM
    hs[tid]  = hd[(long)b * NH + tid];
    vts[tid] = vt[tid];
    __syncthreads();

    // blend2[w] = h . W2[w,:]  via transposed weights (coalesced)
    float acc = 0.f;
#pragma unroll 8
    for (int k = 0; k < NH; k++) acc += hs[k] * g_W2t[k * NW + tid];
    b2s[tid] = acc;
    __syncthreads();

    // scores over T, one warp per t (strided)
    for (int tt = warp; tt < NT; tt += 8) {
        const float* bl = &g_blend1[((long)b * NT + tt) * NW];
        float s = 0.f;
#pragma unroll
        for (int q = 0; q < NW / 32; q++) {
            int w = lane + q * 32;
            s += fast_tanh(bl[w] + b2s[w]) * vts[w];
        }
#pragma unroll
        for (int o = 16; o; o >>= 1) s += __shfl_down_sync(0xffffffffu, s, o);
        if (lane == 0) sc[tt] = g_mask[b * NT + tt] ? NEG_FILLF : s;
    }
    __syncthreads();

    // argmax (first occurrence of max, matching jnp.argmax)
    if (tid == 0) {
        float mx = sc[0]; int mi = 0;
        for (int tt = 1; tt < NT; tt++)
            if (sc[tt] > mx) { mx = sc[tt]; mi = tt; }
        sel_s = mi; mx_s = mx;
    }
    __syncthreads();

    // softmax with clamp
    float e = (tid < NT) ? __expf(sc[tid] - mx_s) : 0.f;
    float s2 = e;
#pragma unroll
    for (int o = 16; o; o >>= 1) s2 += __shfl_down_sync(0xffffffffu, s2, o);
    if (lane == 0) red[warp] = s2;
    __syncthreads();
    if (tid == 0) {
        float tot = 0.f;
        for (int w = 0; w < 8; w++) tot += red[w];
        tot_s = tot;
    }
    __syncthreads();
    if (tid < NT) {
        float p = e / tot_s;
        if (p < PROB_MINF) p = PROB_MINF;
        out[((long)b * NT + step) * NT + tid] = p;
    }

    // mask update AFTER probs (matches reference ordering) + gather next input
    int sel = sel_s;
    if (tid == 0) g_mask[b * NT + sel] = 1;
    if (tid < ND) g_decin[(long)b * ND + tid] = targets[((long)b * NT + sel) * ND + tid];
}

// ---------------- launch ----------------
extern "C" void kernel_launch(void* const* d_in, const int* in_sizes, int n_in,
                              void* d_out, int out_size) {
    const float* targets = (const float*)d_in[0];
    const float* h0      = (const float*)d_in[1];
    const float* c0      = (const float*)d_in[2];
    const float* ewih    = (const float*)d_in[3];
    const float* ewhh    = (const float*)d_in[4];
    const float* ebih    = (const float*)d_in[5];
    const float* ebhh    = (const float*)d_in[6];
    const float* dwih    = (const float*)d_in[7];
    const float* dwhh    = (const float*)d_in[8];
    const float* dbih    = (const float*)d_in[9];
    const float* dbhh    = (const float*)d_in[10];
    const float* W1      = (const float*)d_in[11];
    const float* W2      = (const float*)d_in[12];
    const float* vt      = (const float*)d_in[13];
    float* out = (float*)d_out;

    init_kernel<<<(NB * NH) / 256, 256>>>(h0, c0);
    prep_kernel<<<(KIN * K4) / 256, 256>>>(ewih, ewhh, ebih, ebhh,
                                           dwih, dwhh, dbih, dbhh, W1, W2);

    dim3 lgrid(K4 / 128, NB / 64);   // (8, 32)
    for (int t = 0; t < NT; t++)
        lstm_step_kernel<<<lgrid, 256>>>(targets, t, 0);

    blend1_kernel<<<dim3(NW / 128, (NB * NT) / 64), 256>>>();   // (2, 3200)

    for (int s = 0; s < NT; s++) {
        lstm_step_kernel<<<lgrid, 256>>>(targets, s, 1);
        attn_kernel<<<NB, 256>>>(targets, vt, out, s);
    }
}